// round 9
// baseline (speedup 1.0000x reference)
#include <cuda_runtime.h>
#include <cstdint>

#define Bdim 4
#define Hdim 512
#define Wdim 512
#define C_TOTAL 25
#define CS (Hdim * Wdim)

typedef unsigned long long u64;

// Layer L weight offset: 18*L*L floats (sum_{k<L} 18*(2k+1)). Total 2592.
__constant__ float cw[2592];
__constant__ float cb[24];

__device__ __forceinline__ void fma2(u64& d, u64 a, u64 b) {
    asm("fma.rn.f32x2 %0, %1, %2, %0;" : "+l"(d) : "l"(a), "l"(b));
}
__device__ __forceinline__ u64 dup2(float v) {
    u64 r; asm("mov.b64 %0, {%1, %1};" : "=l"(r) : "f"(v)); return r;
}
__device__ __forceinline__ u64 pack2(float lo, float hi) {
    u64 r; asm("mov.b64 %0, {%1, %2};" : "=l"(r) : "f"(lo), "f"(hi)); return r;
}
__device__ __forceinline__ void unpack2(u64 v, float& lo, float& hi) {
    asm("mov.b64 {%0, %1}, %2;" : "=f"(lo), "=f"(hi) : "l"(v));
}
__device__ __forceinline__ int refl(int x) {        // reflect, H == W == 512
    return x < 0 ? -x : (x >= 512 ? 1022 - x : x);
}

// ---------------------------------------------------------------------------
// ODD-D: C=1 column, out-channel-pair f32x2 acc. Warp = R rows x 32 cols.
// Block = 128 thr = 4 row-groups. Explicit register prefetch pipeline (PF=6).
// ---------------------------------------------------------------------------
template<int L, int N_IN, int D, int R>
__global__ __launch_bounds__(128)
void conv_odd(const float* __restrict__ g, float* __restrict__ outg)
{
    constexpr int OFF = 18 * L * L;
    constexpr int NJ = R + 2 * D;
    constexpr int PF = (NJ < 6) ? NJ : 6;

    const int tc = threadIdx.x & 31;
    const int rg = threadIdx.x >> 5;
    const int w  = blockIdx.x * 32 + tc;
    const int r0 = blockIdx.y * (4 * R) + rg * R;
    const int b  = blockIdx.z;

    const int wl = refl(w - D);
    const int wr = refl(w + D);

    u64 acc[R];
    {
        u64 bp = pack2(cb[2 * L], cb[2 * L + 1]);
        #pragma unroll
        for (int m = 0; m < R; ++m) acc[m] = bp;
    }

    const float* plane0 = g + (size_t)(b * C_TOTAL) * CS;

    #pragma unroll 1
    for (int ic = 0; ic < N_IN; ++ic) {
        const float* plane = plane0 + (size_t)ic * CS;
        u64 wp[9];
        #pragma unroll
        for (int k = 0; k < 9; ++k)
            wp[k] = pack2(cw[OFF + ic * 9 + k], cw[OFF + 9 * N_IN + ic * 9 + k]);

        float pl[PF], pc[PF], pr[PF];
        #pragma unroll
        for (int s = 0; s < PF; ++s) {
            const float* row = plane + ((size_t)refl(r0 - D + s) << 9);
            pl[s] = __ldg(row + wl); pc[s] = __ldg(row + w); pr[s] = __ldg(row + wr);
        }

        #pragma unroll
        for (int j = 0; j < NJ; ++j) {
            u64 vl = dup2(pl[j % PF]);
            u64 vc = dup2(pc[j % PF]);
            u64 vr = dup2(pr[j % PF]);
            if (j + PF < NJ) {
                const float* row = plane + ((size_t)refl(r0 - D + j + PF) << 9);
                pl[j % PF] = __ldg(row + wl);
                pc[j % PF] = __ldg(row + w);
                pr[j % PF] = __ldg(row + wr);
            }
            if (j < R) {
                fma2(acc[j], wp[0], vl); fma2(acc[j], wp[1], vc); fma2(acc[j], wp[2], vr);
            }
            if (j >= D && j < R + D) {
                fma2(acc[j - D], wp[3], vl); fma2(acc[j - D], wp[4], vc); fma2(acc[j - D], wp[5], vr);
            }
            if (j >= 2 * D) {
                fma2(acc[j - 2 * D], wp[6], vl); fma2(acc[j - 2 * D], wp[7], vc); fma2(acc[j - 2 * D], wp[8], vr);
            }
        }
    }

    float* o = outg + ((size_t)(b * C_TOTAL + N_IN)) * CS + (size_t)r0 * Wdim + w;
    #pragma unroll
    for (int m = 0; m < R; ++m) {
        float lo, hi;
        unpack2(acc[m], lo, hi);
        o[(size_t)m * Wdim]      = fmaxf(lo, 0.f);
        o[CS + (size_t)m * Wdim] = fmaxf(hi, 0.f);
    }
}

// ---------------------------------------------------------------------------
// EVEN-D: C=2 spatial f32x2 (aligned LDG.64 taps, no packing MOVs), both out
// channels. Warp = R rows x 64 cols. Block = 128 thr = 4 row-groups. PF=4.
// ---------------------------------------------------------------------------
template<int L, int N_IN, int D, int R, bool EDGE>
__device__ __forceinline__ void tile_even(const float* __restrict__ g,
                                          float* __restrict__ outg,
                                          int w, int r0, int b)
{
    constexpr int OFF = 18 * L * L;
    constexpr int NJ = R + 2 * D;
    constexpr int PF = (NJ < 4) ? NJ : 4;

    u64 accA[R], accB[R];
    {
        u64 bA = dup2(cb[2 * L]), bB = dup2(cb[2 * L + 1]);
        #pragma unroll
        for (int m = 0; m < R; ++m) { accA[m] = bA; accB[m] = bB; }
    }

    const float* plane0 = g + (size_t)(b * C_TOTAL) * CS;

    #pragma unroll 1
    for (int ic = 0; ic < N_IN; ++ic) {
        const float* plane = plane0 + (size_t)ic * CS;
        u64 wA[9], wB[9];
        #pragma unroll
        for (int k = 0; k < 9; ++k) {
            wA[k] = dup2(cw[OFF + ic * 9 + k]);
            wB[k] = dup2(cw[OFF + 9 * N_IN + ic * 9 + k]);
        }

        u64 pl[PF], pc[PF], pr[PF];
        auto ldrow = [&](int s, int slot) {
            const float* row = plane + ((size_t)refl(r0 - D + s) << 9);
            pc[slot] = __ldg((const u64*)(row + w));
            if (EDGE) {
                pl[slot] = pack2(__ldg(row + refl(w - D)), __ldg(row + refl(w + 1 - D)));
                pr[slot] = pack2(__ldg(row + refl(w + D)), __ldg(row + refl(w + 1 + D)));
            } else {
                pl[slot] = __ldg((const u64*)(row + (w - D)));
                pr[slot] = __ldg((const u64*)(row + (w + D)));
            }
        };

        #pragma unroll
        for (int s = 0; s < PF; ++s) ldrow(s, s);

        #pragma unroll
        for (int j = 0; j < NJ; ++j) {
            u64 vl = pl[j % PF], vc = pc[j % PF], vr = pr[j % PF];
            if (j + PF < NJ) ldrow(j + PF, j % PF);
            if (j < R) {
                fma2(accA[j], wA[0], vl); fma2(accA[j], wA[1], vc); fma2(accA[j], wA[2], vr);
                fma2(accB[j], wB[0], vl); fma2(accB[j], wB[1], vc); fma2(accB[j], wB[2], vr);
            }
            if (j >= D && j < R + D) {
                fma2(accA[j - D], wA[3], vl); fma2(accA[j - D], wA[4], vc); fma2(accA[j - D], wA[5], vr);
                fma2(accB[j - D], wB[3], vl); fma2(accB[j - D], wB[4], vc); fma2(accB[j - D], wB[5], vr);
            }
            if (j >= 2 * D) {
                fma2(accA[j - 2 * D], wA[6], vl); fma2(accA[j - 2 * D], wA[7], vc); fma2(accA[j - 2 * D], wA[8], vr);
                fma2(accB[j - 2 * D], wB[6], vl); fma2(accB[j - 2 * D], wB[7], vc); fma2(accB[j - 2 * D], wB[8], vr);
            }
        }
    }

    float* o = outg + ((size_t)(b * C_TOTAL + N_IN)) * CS + (size_t)r0 * Wdim + w;
    #pragma unroll
    for (int m = 0; m < R; ++m) {
        float lo, hi;
        unpack2(accA[m], lo, hi);
        *(float2*)(o + (size_t)m * Wdim) = make_float2(fmaxf(lo, 0.f), fmaxf(hi, 0.f));
        unpack2(accB[m], lo, hi);
        *(float2*)(o + CS + (size_t)m * Wdim) = make_float2(fmaxf(lo, 0.f), fmaxf(hi, 0.f));
    }
}

template<int L, int N_IN, int D, int R>
__global__ __launch_bounds__(128)
void conv_even(const float* __restrict__ g, float* __restrict__ outg)
{
    const int tc = threadIdx.x & 31;
    const int rg = threadIdx.x >> 5;
    const int w  = blockIdx.x * 64 + 2 * tc;
    const int r0 = blockIdx.y * (4 * R) + rg * R;
    const int b  = blockIdx.z;

    if (blockIdx.x == 0 || blockIdx.x == 7)
        tile_even<L, N_IN, D, R, true >(g, outg, w, r0, b);
    else
        tile_even<L, N_IN, D, R, false>(g, outg, w, r0, b);
}

__global__ void copy_in_kernel(const float4* __restrict__ x, float4* __restrict__ out) {
    int idx = blockIdx.x * blockDim.x + threadIdx.x;
    const int P4 = CS / 4;
    if (idx >= Bdim * P4) return;
    int b = idx / P4;
    int p = idx - b * P4;
    out[(size_t)b * (C_TOTAL * P4) + p] = x[idx];
}

extern "C" void kernel_launch(void* const* d_in, const int* in_sizes, int n_in,
                              void* d_out, int out_size) {
    const float* x = (const float*)d_in[0];
    float* out = (float*)d_out;

    for (int i = 0; i < 12; ++i) {
        int nin = 1 + 2 * i;
        cudaMemcpyToSymbolAsync(cw, d_in[2 + i], (size_t)(18 * nin) * 4,
                                (size_t)(18 * i * i) * 4, cudaMemcpyDeviceToDevice, 0);
    }
    cudaMemcpyToSymbolAsync(cb, d_in[1], 24 * 4, 0, cudaMemcpyDeviceToDevice, 0);

    {
        int total4 = Bdim * CS / 4;
        copy_in_kernel<<<(total4 + 255) / 256, 256>>>((const float4*)x, (float4*)out);
    }

    // Odd-D: C=1. Light (D<5): R=16 (2048 warps). Heavy: R=32 (1024 warps).
    // Even-D: C=2. Light: R=8  (2048 warps). Heavy: R=16 (1024 warps).
    conv_odd <0,  1,  1, 16><<<dim3(16, 8, Bdim), 128>>>(out, out);
    conv_even<1,  3,  2,  8><<<dim3( 8, 16, Bdim), 128>>>(out, out);
    conv_odd <2,  5,  3, 16><<<dim3(16, 8, Bdim), 128>>>(out, out);
    conv_even<3,  7,  4,  8><<<dim3( 8, 16, Bdim), 128>>>(out, out);
    conv_odd <4,  9,  5, 32><<<dim3(16, 4, Bdim), 128>>>(out, out);
    conv_even<5, 11,  6, 16><<<dim3( 8,  8, Bdim), 128>>>(out, out);
    conv_odd <6, 13,  7, 32><<<dim3(16, 4, Bdim), 128>>>(out, out);
    conv_even<7, 15,  8, 16><<<dim3( 8,  8, Bdim), 128>>>(out, out);
    conv_odd <8, 17,  9, 32><<<dim3(16, 4, Bdim), 128>>>(out, out);
    conv_even<9, 19, 10, 16><<<dim3( 8,  8, Bdim), 128>>>(out, out);
    conv_odd <10, 21, 11, 32><<<dim3(16, 4, Bdim), 128>>>(out, out);
    conv_even<11, 23, 12, 16><<<dim3( 8,  8, Bdim), 128>>>(out, out);
}

// round 10
// speedup vs baseline: 1.8766x; 1.8766x over previous
#include <cuda_runtime.h>

// MSD block: 12 dilated 3x3 convs (reflect pad, ReLU), channels concatenated.
// Output buffer d_out holds the full (4, 25, 512, 512) concat tensor; each layer
// kernel reads channels [0, n_in) and writes channels [n_in, n_in+2) in place.
// R1-proven body; R=16 everywhere to double heavy-layer warp supply.

#define Bdim 4
#define Hdim 512
#define Wdim 512
#define C_TOTAL 25
#define CS (Hdim * Wdim)

typedef unsigned long long u64;

__device__ __forceinline__ void fma2(u64& d, u64 a, u64 b) {
    asm("fma.rn.f32x2 %0, %1, %2, %0;" : "+l"(d) : "l"(a), "l"(b));
}
__device__ __forceinline__ u64 dup2(float v) {
    u64 r; asm("mov.b64 %0, {%1, %1};" : "=l"(r) : "f"(v)); return r;
}
__device__ __forceinline__ u64 pack2(float lo, float hi) {
    u64 r; asm("mov.b64 %0, {%1, %2};" : "=l"(r) : "f"(lo), "f"(hi)); return r;
}
__device__ __forceinline__ void unpack2(u64 v, float& lo, float& hi) {
    asm("mov.b64 {%0, %1}, %2;" : "=f"(lo), "=f"(hi) : "l"(v));
}

// Input-row-stationary conv body: thread owns output column w, rows [r0, r0+R).
// For each input channel, sweep input rows r0-D .. r0+R-1+D once; each row's 3
// kw-taps (w-D, w, w+D) feed up to 3 kh accumulator rows x 2 packed out channels.
template<int N_IN, int D, int R, bool REFL>
__device__ __forceinline__ void conv_body(const float* __restrict__ buf,
                                          float* __restrict__ outp,
                                          const u64* __restrict__ ws2,
                                          u64 bias2, int b, int r0, int w) {
    int wl = w - D; if (wl < 0) wl = -wl;                      // reflect cols
    int wr = w + D; if (wr >= Wdim) wr = 2 * Wdim - 2 - wr;

    u64 acc[R];
    #pragma unroll
    for (int m = 0; m < R; ++m) acc[m] = bias2;

    #pragma unroll 1
    for (int ic = 0; ic < N_IN; ++ic) {
        const float* plane = buf + ((size_t)b * C_TOTAL + ic) * CS;
        const u64* wrow = ws2 + ic * 9;
        u64 w00 = wrow[0], w01 = wrow[1], w02 = wrow[2];
        u64 w10 = wrow[3], w11 = wrow[4], w12 = wrow[5];
        u64 w20 = wrow[6], w21 = wrow[7], w22 = wrow[8];
        #pragma unroll
        for (int j = 0; j < R + 2 * D; ++j) {
            int x = r0 - D + j;
            int xr = x;
            if (REFL) {
                if (x < 0) xr = -x;
                else if (x >= Hdim) xr = 2 * Hdim - 2 - x;
            }
            const float* row = plane + (size_t)xr * Wdim;
            u64 vl = dup2(__ldg(row + wl));
            u64 vc = dup2(__ldg(row + w));
            u64 vr = dup2(__ldg(row + wr));
            // kh=0 contributes to out row m=j ; kh=1 -> m=j-D ; kh=2 -> m=j-2D
            if (j < R) {
                fma2(acc[j], w00, vl); fma2(acc[j], w01, vc); fma2(acc[j], w02, vr);
            }
            if (j >= D && j < R + D) {
                fma2(acc[j - D], w10, vl); fma2(acc[j - D], w11, vc); fma2(acc[j - D], w12, vr);
            }
            if (j >= 2 * D) {   // j - 2D < R always holds since j < R + 2D
                fma2(acc[j - 2 * D], w20, vl); fma2(acc[j - 2 * D], w21, vc); fma2(acc[j - 2 * D], w22, vr);
            }
        }
    }

    float* o0 = outp + ((size_t)b * C_TOTAL + N_IN) * CS + (size_t)r0 * Wdim + w;
    #pragma unroll
    for (int m = 0; m < R; ++m) {
        float lo, hi; unpack2(acc[m], lo, hi);
        o0[(size_t)m * Wdim]      = fmaxf(lo, 0.f);
        o0[CS + (size_t)m * Wdim] = fmaxf(hi, 0.f);
    }
}

template<int N_IN, int D, int R>
__global__ __launch_bounds__(128)
void conv_layer(const float* __restrict__ buf, float* __restrict__ outp,
                const float* __restrict__ wgt, const float* __restrict__ bias,
                int layer) {
    __shared__ u64 ws2[N_IN * 9];
    __shared__ u64 bsh;
    int tid = threadIdx.x;
    for (int i = tid; i < N_IN * 9; i += 128)
        ws2[i] = pack2(wgt[i], wgt[N_IN * 9 + i]);   // pack (oc0, oc1) weight pair
    if (tid == 0) bsh = pack2(bias[2 * layer], bias[2 * layer + 1]);
    __syncthreads();

    int w  = blockIdx.x * 128 + tid;
    int r0 = blockIdx.y * R;
    int b  = blockIdx.z;
    u64 bias2 = bsh;

    bool interior = (r0 >= D) && (r0 + R + D <= Hdim);
    if (interior) conv_body<N_IN, D, R, false>(buf, outp, ws2, bias2, b, r0, w);
    else          conv_body<N_IN, D, R, true >(buf, outp, ws2, bias2, b, r0, w);
}

// Copy x (4,1,512,512) into channel 0 of the 25-channel output buffer.
__global__ void copy_in_kernel(const float4* __restrict__ x, float4* __restrict__ out) {
    int idx = blockIdx.x * blockDim.x + threadIdx.x;      // over B*CS/4
    const int P4 = CS / 4;
    if (idx >= Bdim * P4) return;
    int b = idx / P4;
    int p = idx - b * P4;
    out[(size_t)b * (C_TOTAL * P4) + p] = x[idx];
}

extern "C" void kernel_launch(void* const* d_in, const int* in_sizes, int n_in,
                              void* d_out, int out_size) {
    const float* x    = (const float*)d_in[0];
    const float* bias = (const float*)d_in[1];
    float* out = (float*)d_out;

    {
        int total4 = Bdim * CS / 4;
        copy_in_kernel<<<(total4 + 255) / 256, 256>>>((const float4*)x, (float4*)out);
    }

    // R=16 for ALL layers: 512 blocks x 4 warps = 2048 warps per layer
    // (13.8/SM) vs 1024 at R=32 — heavy layers were warp-supply starved.
#define LAYER(i, NIN, DD, RR) \
    conv_layer<NIN, DD, RR><<<dim3(Wdim / 128, Hdim / RR, Bdim), 128>>>( \
        out, out, (const float*)d_in[2 + (i)], bias, (i))

    LAYER(0,  1,  1, 16);
    LAYER(1,  3,  2, 16);
    LAYER(2,  5,  3, 16);
    LAYER(3,  7,  4, 16);
    LAYER(4,  9,  5, 16);
    LAYER(5,  11, 6, 16);
    LAYER(6,  13, 7, 16);
    LAYER(7,  15, 8, 16);
    LAYER(8,  17, 9, 16);
    LAYER(9,  19, 10, 16);
    LAYER(10, 21, 11, 16);
    LAYER(11, 23, 12, 16);
#undef LAYER
}